// round 1
// baseline (speedup 1.0000x reference)
#include <cuda_runtime.h>

// Problem constants
#define B_  256
#define I_  128
#define J_  128
#define H_  32
#define F_  7
#define ITILE 16
#define IBLKS (I_ / ITILE)   // 8

// Scratch (allocation-free rule: __device__ globals)
__device__ float g_feats[I_ * 8 * B_];         // [i][f(0..7, f7 unused)][b]
__device__ float g_partial[IBLKS * B_ * J_];   // [ib][j][b]

// Kernel 1: features per (b,i): [x, sin(x), sin(2x), sin(4x), cos(x), cos(2x), cos(4x)]
__global__ void feats_kernel(const float* __restrict__ x) {
    int t = blockIdx.x * blockDim.x + threadIdx.x;
    if (t >= B_ * I_) return;
    int b = t & (B_ - 1);
    int i = t >> 8;
    float xi = x[b * I_ + i];
    float s1, c1, s2, c2, s4, c4;
    __sincosf(xi, &s1, &c1);
    __sincosf(2.0f * xi, &s2, &c2);
    __sincosf(4.0f * xi, &s4, &c4);
    float* fp = g_feats + i * (8 * B_) + b;
    fp[0 * B_] = xi;
    fp[1 * B_] = s1;
    fp[2 * B_] = s2;
    fp[3 * B_] = s4;
    fp[4 * B_] = c1;
    fp[5 * B_] = c2;
    fp[6 * B_] = c4;
}

// Kernel 2: per-(i-tile, j) block; thread = b. Each weight element read from DRAM exactly once.
__global__ __launch_bounds__(256) void kan_main_kernel(
    const float* __restrict__ W1,   // [I,J,H,7]
    const float* __restrict__ W2,   // [I,J,1,H]
    const float* __restrict__ B1,   // [I,J,H]
    const float* __restrict__ B2)   // [I,J,1]
{
    __shared__ float w1s[ITILE][H_][8];  // [il][h][f0..f6, f7=B1]
    __shared__ float w2s[ITILE][H_];
    __shared__ float b2s[ITILE];

    const int j   = blockIdx.y;
    const int i0  = blockIdx.x * ITILE;
    const int tid = threadIdx.x;

    // Stage W1 (+B1 packed in lane 7) and W2, B2 into smem
    for (int idx = tid; idx < ITILE * H_ * F_; idx += 256) {
        int il = idx / (H_ * F_);
        int r  = idx % (H_ * F_);
        int h  = r / F_;
        int f  = r % F_;
        w1s[il][h][f] = W1[((size_t)(i0 + il) * J_ + j) * (H_ * F_) + r];
    }
    for (int idx = tid; idx < ITILE * H_; idx += 256) {
        int il = idx / H_;
        int h  = idx % H_;
        size_t base = ((size_t)(i0 + il) * J_ + j) * H_ + h;
        w1s[il][h][7] = B1[base];
        w2s[il][h]    = W2[base];
    }
    if (tid < ITILE) b2s[tid] = B2[(size_t)(i0 + tid) * J_ + j];
    __syncthreads();

    const int b = tid;
    float acc = 0.0f;

    for (int il = 0; il < ITILE; il++) {
        const float* fp = g_feats + (i0 + il) * (8 * B_) + b;
        float f0 = fp[0 * B_];
        float f1 = fp[1 * B_];
        float f2 = fp[2 * B_];
        float f3 = fp[3 * B_];
        float f4 = fp[4 * B_];
        float f5 = fp[5 * B_];
        float f6 = fp[6 * B_];
        acc += b2s[il];

        #pragma unroll
        for (int h = 0; h < H_; h++) {
            float4 wa = *(const float4*)&w1s[il][h][0];
            float4 wb = *(const float4*)&w1s[il][h][4];
            float t = wb.w;                    // B1
            t = fmaf(f0, wa.x, t);
            t = fmaf(f1, wa.y, t);
            t = fmaf(f2, wa.z, t);
            t = fmaf(f3, wa.w, t);
            t = fmaf(f4, wb.x, t);
            t = fmaf(f5, wb.y, t);
            t = fmaf(f6, wb.z, t);
            // silu(t) = t / (1 + e^{-t}); exact-ish (EX2 + RCP)
            float e = __expf(-t);
            float s = __fdividef(t, 1.0f + e);
            acc = fmaf(s, w2s[il][h], acc);
        }
    }

    // Partial per i-tile, layout [ib][j][b] so stores are coalesced across b
    g_partial[blockIdx.x * (B_ * J_) + j * B_ + b] = acc;
}

// Kernel 3: reduce the 8 i-tile partials, write out[b*J + j]
__global__ void reduce_kernel(float* __restrict__ out) {
    int t = blockIdx.x * blockDim.x + threadIdx.x;
    if (t >= B_ * J_) return;
    int b = t >> 7;        // t = b*J + j
    int j = t & (J_ - 1);
    float s = 0.0f;
    #pragma unroll
    for (int k = 0; k < IBLKS; k++)
        s += g_partial[k * (B_ * J_) + j * B_ + b];
    out[t] = s;
}

extern "C" void kernel_launch(void* const* d_in, const int* in_sizes, int n_in,
                              void* d_out, int out_size) {
    const float* x  = (const float*)d_in[0];
    const float* W1 = (const float*)d_in[1];
    const float* W2 = (const float*)d_in[2];
    const float* B1 = (const float*)d_in[3];
    const float* B2 = (const float*)d_in[4];
    float* out = (float*)d_out;

    feats_kernel<<<(B_ * I_ + 255) / 256, 256>>>(x);
    kan_main_kernel<<<dim3(IBLKS, J_), 256>>>(W1, W2, B1, B2);
    reduce_kernel<<<(B_ * J_ + 255) / 256, 256>>>(out);
}

// round 2
// speedup vs baseline: 1.1681x; 1.1681x over previous
#include <cuda_runtime.h>

// Problem constants
#define B_  256
#define I_  128
#define J_  128
#define H_  32
#define F_  7
#define ITILE 16
#define IBLKS (I_ / ITILE)   // 8
#define HP_ (H_ / 2)         // 16 h-pairs

// Scratch (allocation-free rule: __device__ globals)
__device__ float g_feats[I_ * 8 * B_];         // [i][f(0..6, 7 unused)][b]
__device__ float g_partial[IBLKS * B_ * J_];   // [ib][j][b]

typedef unsigned long long u64;

__device__ __forceinline__ u64 pk2(float lo, float hi) {
    u64 r; asm("mov.b64 %0, {%1,%2};" : "=l"(r) : "f"(lo), "f"(hi)); return r;
}
__device__ __forceinline__ void unpk2(u64 v, float& lo, float& hi) {
    asm("mov.b64 {%0,%1}, %2;" : "=f"(lo), "=f"(hi) : "l"(v));
}
__device__ __forceinline__ u64 ffma2(u64 a, u64 b, u64 c) {
    u64 d; asm("fma.rn.f32x2 %0, %1, %2, %3;" : "=l"(d) : "l"(a), "l"(b), "l"(c)); return d;
}
__device__ __forceinline__ float tanh_hw(float x) {
    float y; asm("tanh.approx.f32 %0, %1;" : "=f"(y) : "f"(x)); return y;
}

// Kernel 1: features [x, sin(x), sin(2x), sin(4x), cos(x), cos(2x), cos(4x)]
// smem-tile transpose: coalesced x loads AND coalesced g_feats stores.
__global__ __launch_bounds__(256) void feats_kernel(const float* __restrict__ x) {
    __shared__ float tile[32][33];
    const int b0 = blockIdx.x * 32;   // grid.x = B/32 = 8
    const int i0 = blockIdx.y * 32;   // grid.y = I/32 = 4
    const int tid = threadIdx.x;

    // load 32b x 32i tile, consecutive threads = consecutive i (coalesced)
    {
        int ic = tid & 31, br = tid >> 5;   // 8 b-rows per pass
        #pragma unroll
        for (int k = 0; k < 4; k++)
            tile[br + 8 * k][ic] = x[(b0 + br + 8 * k) * I_ + (i0 + ic)];
    }
    __syncthreads();
    // compute + store, consecutive threads = consecutive b (coalesced stores)
    {
        int bc = tid & 31, ir = tid >> 5;
        #pragma unroll
        for (int k = 0; k < 4; k++) {
            int il = ir + 8 * k;
            float xi = tile[bc][il];
            float s1, c1, s2, c2, s4, c4;
            __sincosf(xi, &s1, &c1);
            __sincosf(2.0f * xi, &s2, &c2);
            __sincosf(4.0f * xi, &s4, &c4);
            float* fp = g_feats + (i0 + il) * (8 * B_) + b0 + bc;
            fp[0 * B_] = xi;
            fp[1 * B_] = s1;
            fp[2 * B_] = s2;
            fp[3 * B_] = s4;
            fp[4 * B_] = c1;
            fp[5 * B_] = c2;
            fp[6 * B_] = c4;
        }
    }
}

// Kernel 2: per-(i-tile, j) block; thread = b. h processed in packed pairs via f32x2.
// smem layout per (il, hp): [f0lo,f0hi, f1lo,f1hi, ..., f6lo,f6hi, B1lo,B1hi, W2lo,W2hi, pad, pad]
//  -> 20 floats = 80 B stride (16B-aligned for LDS.128).
__global__ __launch_bounds__(256) void kan_main_kernel(
    const float* __restrict__ W1,   // [I,J,H,7]
    const float* __restrict__ W2,   // [I,J,1,H]
    const float* __restrict__ B1,   // [I,J,H]
    const float* __restrict__ B2)   // [I,J,1]
{
    __shared__ __align__(16) float ws[ITILE][HP_][20];
    __shared__ float b2s[ITILE];

    const int j   = blockIdx.y;
    const int i0  = blockIdx.x * ITILE;
    const int tid = threadIdx.x;

    // Stage W1 (coalesced global reads, scattered smem writes)
    for (int idx = tid; idx < ITILE * H_ * F_; idx += 256) {
        int il = idx / (H_ * F_);
        int r  = idx % (H_ * F_);
        int h  = r / F_;
        int f  = r % F_;
        ws[il][h >> 1][2 * f + (h & 1)] = W1[((size_t)(i0 + il) * J_ + j) * (H_ * F_) + r];
    }
    // Stage B1 (slot 14/15) and W2 (slot 16/17)
    for (int idx = tid; idx < ITILE * H_; idx += 256) {
        int il = idx / H_;
        int h  = idx % H_;
        size_t base = ((size_t)(i0 + il) * J_ + j) * H_ + h;
        ws[il][h >> 1][14 + (h & 1)] = B1[base];
        ws[il][h >> 1][16 + (h & 1)] = W2[base];
    }
    if (tid < ITILE) b2s[tid] = B2[(size_t)(i0 + tid) * J_ + j];
    __syncthreads();

    const int b = tid;
    u64 acc2 = 0ull;       // packed (0.f, 0.f)
    float accb = 0.0f;

    for (int il = 0; il < ITILE; il++) {
        const float* fp = g_feats + (i0 + il) * (8 * B_) + b;
        float a0 = fp[0 * B_];
        float a1 = fp[1 * B_];
        float a2 = fp[2 * B_];
        float a3 = fp[3 * B_];
        float a4 = fp[4 * B_];
        float a5 = fp[5 * B_];
        float a6 = fp[6 * B_];
        u64 F0 = pk2(a0, a0);
        u64 F1 = pk2(a1, a1);
        u64 F2 = pk2(a2, a2);
        u64 F3 = pk2(a3, a3);
        u64 F4 = pk2(a4, a4);
        u64 F5 = pk2(a5, a5);
        u64 F6 = pk2(a6, a6);
        accb += b2s[il];

        #pragma unroll
        for (int hp = 0; hp < HP_; hp++) {
            const float4* p = (const float4*)&ws[il][hp][0];
            float4 qa = p[0];                         // f0 pair, f1 pair
            float4 qb = p[1];                         // f2 pair, f3 pair
            float4 qc = p[2];                         // f4 pair, f5 pair
            float4 qd = p[3];                         // f6 pair, B1 pair
            float2 w2p = *(const float2*)&ws[il][hp][16];

            u64 t = ffma2(F0, pk2(qa.x, qa.y), pk2(qd.z, qd.w));
            t = ffma2(F1, pk2(qa.z, qa.w), t);
            t = ffma2(F2, pk2(qb.x, qb.y), t);
            t = ffma2(F3, pk2(qb.z, qb.w), t);
            t = ffma2(F4, pk2(qc.x, qc.y), t);
            t = ffma2(F5, pk2(qc.z, qc.w), t);
            t = ffma2(F6, pk2(qd.x, qd.y), t);

            float t0, t1; unpk2(t, t0, t1);
            // silu(t) = u + u*tanh(u), u = t/2  (1 MUFU per element)
            float u0 = 0.5f * t0;
            float u1 = 0.5f * t1;
            float s0 = fmaf(u0, tanh_hw(u0), u0);
            float s1 = fmaf(u1, tanh_hw(u1), u1);

            acc2 = ffma2(pk2(s0, s1), pk2(w2p.x, w2p.y), acc2);
        }
    }

    float alo, ahi; unpk2(acc2, alo, ahi);
    g_partial[blockIdx.x * (B_ * J_) + j * B_ + b] = alo + ahi + accb;
}

// Kernel 3: reduce the 8 i-tile partials. Coalesced reads (consecutive b),
// scattered stores (once).
__global__ void reduce_kernel(float* __restrict__ out) {
    int t = blockIdx.x * blockDim.x + threadIdx.x;
    if (t >= B_ * J_) return;
    int b = t & (B_ - 1);
    int j = t >> 8;                 // t = j*B + b
    float s = 0.0f;
    #pragma unroll
    for (int k = 0; k < IBLKS; k++)
        s += g_partial[k * (B_ * J_) + j * B_ + b];
    out[b * J_ + j] = s;
}

extern "C" void kernel_launch(void* const* d_in, const int* in_sizes, int n_in,
                              void* d_out, int out_size) {
    const float* x  = (const float*)d_in[0];
    const float* W1 = (const float*)d_in[1];
    const float* W2 = (const float*)d_in[2];
    const float* B1 = (const float*)d_in[3];
    const float* B2 = (const float*)d_in[4];
    float* out = (float*)d_out;

    feats_kernel<<<dim3(B_ / 32, I_ / 32), 256>>>(x);
    kan_main_kernel<<<dim3(IBLKS, J_), 256>>>(W1, W2, B1, B2);
    reduce_kernel<<<(B_ * J_ + 255) / 256, 256>>>(out);
}

// round 3
// speedup vs baseline: 1.3688x; 1.1719x over previous
#include <cuda_runtime.h>

// Problem constants
#define B_  256
#define I_  128
#define J_  128
#define H_  32
#define F_  7
#define ITILE 16
#define IBLKS (I_ / ITILE)   // 8
#define HP_ (H_ / 2)         // 16 h-pairs

// Scratch (allocation-free rule: __device__ globals)
__device__ float g_feats[I_ * 8 * B_];         // [i][f(0..6, 7 unused)][b]
__device__ float g_partial[IBLKS * B_ * J_];   // [ib][j][b]

typedef unsigned long long u64;

__device__ __forceinline__ u64 pk2(float lo, float hi) {
    u64 r; asm("mov.b64 %0, {%1,%2};" : "=l"(r) : "f"(lo), "f"(hi)); return r;
}
__device__ __forceinline__ void unpk2(u64 v, float& lo, float& hi) {
    asm("mov.b64 {%0,%1}, %2;" : "=f"(lo), "=f"(hi) : "l"(v));
}
__device__ __forceinline__ u64 ffma2(u64 a, u64 b, u64 c) {
    u64 d; asm("fma.rn.f32x2 %0, %1, %2, %3;" : "=l"(d) : "l"(a), "l"(b), "l"(c)); return d;
}
__device__ __forceinline__ u64 fmul2(u64 a, u64 b) {
    u64 d; asm("mul.rn.f32x2 %0, %1, %2;" : "=l"(d) : "l"(a), "l"(b)); return d;
}
__device__ __forceinline__ float tanh_hw(float x) {
    float y; asm("tanh.approx.f32 %0, %1;" : "=f"(y) : "f"(x)); return y;
}

// Kernel 1: features [x, sin(x), sin(2x), sin(4x), cos(x), cos(2x), cos(4x)]
__global__ __launch_bounds__(256) void feats_kernel(const float* __restrict__ x) {
    __shared__ float tile[32][33];
    const int b0 = blockIdx.x * 32;   // grid.x = B/32 = 8
    const int i0 = blockIdx.y * 32;   // grid.y = I/32 = 4
    const int tid = threadIdx.x;

    {
        int ic = tid & 31, br = tid >> 5;
        #pragma unroll
        for (int k = 0; k < 4; k++)
            tile[br + 8 * k][ic] = x[(b0 + br + 8 * k) * I_ + (i0 + ic)];
    }
    __syncthreads();
    {
        int bc = tid & 31, ir = tid >> 5;
        #pragma unroll
        for (int k = 0; k < 4; k++) {
            int il = ir + 8 * k;
            float xi = tile[bc][il];
            float s1, c1, s2, c2, s4, c4;
            __sincosf(xi, &s1, &c1);
            __sincosf(2.0f * xi, &s2, &c2);
            __sincosf(4.0f * xi, &s4, &c4);
            float* fp = g_feats + (i0 + il) * (8 * B_) + b0 + bc;
            fp[0 * B_] = xi;
            fp[1 * B_] = s1;
            fp[2 * B_] = s2;
            fp[3 * B_] = s4;
            fp[4 * B_] = c1;
            fp[5 * B_] = c2;
            fp[6 * B_] = c4;
        }
    }
}

// Kernel 2: 128 threads; thread owns batches (tid, tid+128). h packed in pairs.
// smem per (il,hp): 20 floats = 80B (16B aligned):
//   [f0lo,f0hi, f1lo,f1hi, ..., f6lo,f6hi, B1lo,B1hi, W2lo,W2hi, pad, pad]
__global__ __launch_bounds__(128) void kan_main_kernel(
    const float* __restrict__ W1,   // [I,J,H,7]
    const float* __restrict__ W2,   // [I,J,1,H]
    const float* __restrict__ B1,   // [I,J,H]
    const float* __restrict__ B2)   // [I,J,1]
{
    __shared__ __align__(16) float ws[ITILE][HP_][20];
    __shared__ float b2s[ITILE];

    const int j   = blockIdx.y;
    const int i0  = blockIdx.x * ITILE;
    const int tid = threadIdx.x;

    for (int idx = tid; idx < ITILE * H_ * F_; idx += 128) {
        int il = idx / (H_ * F_);
        int r  = idx % (H_ * F_);
        int h  = r / F_;
        int f  = r % F_;
        ws[il][h >> 1][2 * f + (h & 1)] = W1[((size_t)(i0 + il) * J_ + j) * (H_ * F_) + r];
    }
    for (int idx = tid; idx < ITILE * H_; idx += 128) {
        int il = idx / H_;
        int h  = idx % H_;
        size_t base = ((size_t)(i0 + il) * J_ + j) * H_ + h;
        ws[il][h >> 1][14 + (h & 1)] = B1[base];
        ws[il][h >> 1][16 + (h & 1)] = W2[base];
    }
    if (tid < ITILE) b2s[tid] = B2[(size_t)(i0 + tid) * J_ + j];
    __syncthreads();

    const u64 HALF2 = pk2(0.5f, 0.5f);
    u64 accA = 0ull, accB = 0ull;
    float bsum = 0.0f;

    for (int il = 0; il < ITILE; il++) {
        const float* fp = g_feats + (i0 + il) * (8 * B_) + tid;
        u64 FA[F_], FB[F_];
        #pragma unroll
        for (int f = 0; f < F_; f++) {
            float va = fp[f * B_];
            float vb = fp[f * B_ + 128];
            FA[f] = pk2(va, va);
            FB[f] = pk2(vb, vb);
        }
        bsum += b2s[il];

        #pragma unroll
        for (int hp = 0; hp < HP_; hp++) {
            const ulonglong2* p = (const ulonglong2*)&ws[il][hp][0];
            ulonglong2 p0 = p[0];   // f0 pair, f1 pair
            ulonglong2 p1 = p[1];   // f2 pair, f3 pair
            ulonglong2 p2 = p[2];   // f4 pair, f5 pair
            ulonglong2 p3 = p[3];   // f6 pair, B1 pair
            u64 w2p = *(const u64*)&ws[il][hp][16];

            u64 tA = ffma2(FA[0], p0.x, p3.y);
            tA = ffma2(FA[1], p0.y, tA);
            tA = ffma2(FA[2], p1.x, tA);
            tA = ffma2(FA[3], p1.y, tA);
            tA = ffma2(FA[4], p2.x, tA);
            tA = ffma2(FA[5], p2.y, tA);
            tA = ffma2(FA[6], p3.x, tA);

            u64 tB = ffma2(FB[0], p0.x, p3.y);
            tB = ffma2(FB[1], p0.y, tB);
            tB = ffma2(FB[2], p1.x, tB);
            tB = ffma2(FB[3], p1.y, tB);
            tB = ffma2(FB[4], p2.x, tB);
            tB = ffma2(FB[5], p2.y, tB);
            tB = ffma2(FB[6], p3.x, tB);

            // silu(t) = u + u*tanh(u), u = t/2  (stay packed except the 2 MUFU)
            u64 uA = fmul2(tA, HALF2);
            u64 uB = fmul2(tB, HALF2);
            float uA0, uA1, uB0, uB1;
            unpk2(uA, uA0, uA1);
            unpk2(uB, uB0, uB1);
            u64 thA = pk2(tanh_hw(uA0), tanh_hw(uA1));
            u64 thB = pk2(tanh_hw(uB0), tanh_hw(uB1));
            u64 sA = ffma2(uA, thA, uA);
            u64 sB = ffma2(uB, thB, uB);

            accA = ffma2(sA, w2p, accA);
            accB = ffma2(sB, w2p, accB);
        }
    }

    float a0, a1, b0v, b1v;
    unpk2(accA, a0, a1);
    unpk2(accB, b0v, b1v);
    float* gp = g_partial + blockIdx.x * (B_ * J_) + j * B_;
    gp[tid]       = a0 + a1 + bsum;
    gp[tid + 128] = b0v + b1v + bsum;
}

// Kernel 3: reduce the 8 i-tile partials.
__global__ void reduce_kernel(float* __restrict__ out) {
    int t = blockIdx.x * blockDim.x + threadIdx.x;
    if (t >= B_ * J_) return;
    int b = t & (B_ - 1);
    int j = t >> 8;                 // t = j*B + b
    float s = 0.0f;
    #pragma unroll
    for (int k = 0; k < IBLKS; k++)
        s += g_partial[k * (B_ * J_) + j * B_ + b];
    out[b * J_ + j] = s;
}

extern "C" void kernel_launch(void* const* d_in, const int* in_sizes, int n_in,
                              void* d_out, int out_size) {
    const float* x  = (const float*)d_in[0];
    const float* W1 = (const float*)d_in[1];
    const float* W2 = (const float*)d_in[2];
    const float* B1 = (const float*)d_in[3];
    const float* B2 = (const float*)d_in[4];
    float* out = (float*)d_out;

    feats_kernel<<<dim3(B_ / 32, I_ / 32), 256>>>(x);
    kan_main_kernel<<<dim3(IBLKS, J_), 128>>>(W1, W2, B1, B2);
    reduce_kernel<<<(B_ * J_ + 255) / 256, 256>>>(out);
}

// round 5
// speedup vs baseline: 1.5292x; 1.1171x over previous
#include <cuda_runtime.h>
#include <cuda_fp16.h>

// Problem constants
#define B_  256
#define I_  128
#define J_  128
#define H_  32
#define F_  7
#define ITILE 16
#define IBLKS (I_ / ITILE)   // 8
#define HP_ (H_ / 2)         // 16 h-pairs

// Scratch (allocation-free rule: __device__ globals)
__device__ unsigned g_feats_h[I_ * 8 * B_];    // [i][f(0..6)][b], half2 (dup) as u32
__device__ float g_partial[IBLKS * B_ * J_];   // [ib][j][b]

__device__ __forceinline__ float tanh_hw(float x) {
    float y; asm("tanh.approx.f32 %0, %1;" : "=f"(y) : "f"(x)); return y;
}
__device__ __forceinline__ __half2 h2(unsigned u) {
    return *reinterpret_cast<__half2*>(&u);
}
__device__ __forceinline__ unsigned dup_h(float v) {
    __half h = __float2half(v);
    __half2 p = __halves2half2(h, h);
    return *reinterpret_cast<unsigned*>(&p);
}

// Kernel 1: features [x, sin(x), sin(2x), sin(4x), cos(x), cos(2x), cos(4x)],
// each stored as a duplicated half2 (u32). smem transpose for coalescing.
__global__ __launch_bounds__(256) void feats_kernel(const float* __restrict__ x) {
    __shared__ float tile[32][33];
    const int b0 = blockIdx.x * 32;   // grid.x = B/32 = 8
    const int i0 = blockIdx.y * 32;   // grid.y = I/32 = 4
    const int tid = threadIdx.x;

    {
        int ic = tid & 31, br = tid >> 5;
        #pragma unroll
        for (int k = 0; k < 4; k++)
            tile[br + 8 * k][ic] = x[(b0 + br + 8 * k) * I_ + (i0 + ic)];
    }
    __syncthreads();
    {
        int bc = tid & 31, ir = tid >> 5;
        #pragma unroll
        for (int k = 0; k < 4; k++) {
            int il = ir + 8 * k;
            float xi = tile[bc][il];
            float s1, c1, s2, c2, s4, c4;
            __sincosf(xi, &s1, &c1);
            __sincosf(2.0f * xi, &s2, &c2);
            __sincosf(4.0f * xi, &s4, &c4);
            unsigned* fp = g_feats_h + (i0 + il) * (8 * B_) + b0 + bc;
            fp[0 * B_] = dup_h(xi);
            fp[1 * B_] = dup_h(s1);
            fp[2 * B_] = dup_h(s2);
            fp[3 * B_] = dup_h(s4);
            fp[4 * B_] = dup_h(c1);
            fp[5 * B_] = dup_h(c2);
            fp[6 * B_] = dup_h(c4);
        }
    }
}

// Kernel 2: 128 threads; thread owns batches (tid, tid+128). h in packed pairs.
// smem per (il,hp): 8 half2 = [0.5*W1 f0..f6 pairs, 0.5*B1 pair] (32B, 16B-aligned)
//                   + float2 W2 pair (UNSCALED: silu(t) = u + u*tanh(u), u = t/2)
__global__ __launch_bounds__(128) void kan_main_kernel(
    const float* __restrict__ W1,   // [I,J,H,7]
    const float* __restrict__ W2,   // [I,J,1,H]
    const float* __restrict__ B1,   // [I,J,H]
    const float* __restrict__ B2)   // [I,J,1]
{
    __shared__ __align__(16) __half w1h[ITILE][HP_][8][2];  // [..][f or 7=B1][h&1]
    __shared__ float w2f[ITILE][HP_][2];
    __shared__ float b2s[ITILE];

    const int j   = blockIdx.y;
    const int i0  = blockIdx.x * ITILE;
    const int tid = threadIdx.x;

    // Stage W1 (pre-scaled by 0.5, converted to half)
    for (int idx = tid; idx < ITILE * H_ * F_; idx += 128) {
        int il = idx / (H_ * F_);
        int r  = idx % (H_ * F_);
        int h  = r / F_;
        int f  = r % F_;
        w1h[il][h >> 1][f][h & 1] =
            __float2half(0.5f * W1[((size_t)(i0 + il) * J_ + j) * (H_ * F_) + r]);
    }
    // Stage B1 (*0.5, half, slot 7) and W2 (fp32, unscaled)
    for (int idx = tid; idx < ITILE * H_; idx += 128) {
        int il = idx / H_;
        int h  = idx % H_;
        size_t base = ((size_t)(i0 + il) * J_ + j) * H_ + h;
        w1h[il][h >> 1][7][h & 1] = __float2half(0.5f * B1[base]);
        w2f[il][h >> 1][h & 1]    = W2[base];
    }
    if (tid < ITILE) b2s[tid] = B2[(size_t)(i0 + tid) * J_ + j];
    __syncthreads();

    float accA = 0.0f, accB = 0.0f;
    float bsum = 0.0f;

    for (int il = 0; il < ITILE; il++) {
        const unsigned* fp = g_feats_h + (i0 + il) * (8 * B_) + tid;
        __half2 FA[F_], FB[F_];
        #pragma unroll
        for (int f = 0; f < F_; f++) {
            FA[f] = h2(fp[f * B_]);
            FB[f] = h2(fp[f * B_ + 128]);
        }
        bsum += b2s[il];

        #pragma unroll
        for (int hp = 0; hp < HP_; hp++) {
            const uint4* p = (const uint4*)&w1h[il][hp][0][0];
            uint4 qa = p[0];   // f0,f1,f2,f3 pairs
            uint4 qb = p[1];   // f4,f5,f6,B1 pairs
            float2 w2p = *(const float2*)&w2f[il][hp][0];

            // u = 0.5*(W1·feats + B1), fp16x2 dot with pre-scaled weights
            __half2 uA2 = __hfma2(FA[0], h2(qa.x), h2(qb.w));
            uA2 = __hfma2(FA[1], h2(qa.y), uA2);
            uA2 = __hfma2(FA[2], h2(qa.z), uA2);
            uA2 = __hfma2(FA[3], h2(qa.w), uA2);
            uA2 = __hfma2(FA[4], h2(qb.x), uA2);
            uA2 = __hfma2(FA[5], h2(qb.y), uA2);
            uA2 = __hfma2(FA[6], h2(qb.z), uA2);

            __half2 uB2 = __hfma2(FB[0], h2(qa.x), h2(qb.w));
            uB2 = __hfma2(FB[1], h2(qa.y), uB2);
            uB2 = __hfma2(FB[2], h2(qa.z), uB2);
            uB2 = __hfma2(FB[3], h2(qa.w), uB2);
            uB2 = __hfma2(FB[4], h2(qb.x), uB2);
            uB2 = __hfma2(FB[5], h2(qb.y), uB2);
            uB2 = __hfma2(FB[6], h2(qb.z), uB2);

            // silu(t) = u + u*tanh(u)  (this IS silu, no extra scaling)
            float uA0 = __low2float(uA2), uA1 = __high2float(uA2);
            float uB0 = __low2float(uB2), uB1 = __high2float(uB2);
            float sA0 = fmaf(uA0, tanh_hw(uA0), uA0);
            float sA1 = fmaf(uA1, tanh_hw(uA1), uA1);
            float sB0 = fmaf(uB0, tanh_hw(uB0), uB0);
            float sB1 = fmaf(uB1, tanh_hw(uB1), uB1);

            accA = fmaf(sA0, w2p.x, accA);
            accA = fmaf(sA1, w2p.y, accA);
            accB = fmaf(sB0, w2p.x, accB);
            accB = fmaf(sB1, w2p.y, accB);
        }
    }

    float* gp = g_partial + blockIdx.x * (B_ * J_) + j * B_;
    gp[tid]       = accA + bsum;
    gp[tid + 128] = accB + bsum;
}

// Kernel 3: reduce the 8 i-tile partials.
__global__ void reduce_kernel(float* __restrict__ out) {
    int t = blockIdx.x * blockDim.x + threadIdx.x;
    if (t >= B_ * J_) return;
    int b = t & (B_ - 1);
    int j = t >> 8;                 // t = j*B + b
    float s = 0.0f;
    #pragma unroll
    for (int k = 0; k < IBLKS; k++)
        s += g_partial[k * (B_ * J_) + j * B_ + b];
    out[b * J_ + j] = s;
}

extern "C" void kernel_launch(void* const* d_in, const int* in_sizes, int n_in,
                              void* d_out, int out_size) {
    const float* x  = (const float*)d_in[0];
    const float* W1 = (const float*)d_in[1];
    const float* W2 = (const float*)d_in[2];
    const float* B1 = (const float*)d_in[3];
    const float* B2 = (const float*)d_in[4];
    float* out = (float*)d_out;

    feats_kernel<<<dim3(B_ / 32, I_ / 32), 256>>>(x);
    kan_main_kernel<<<dim3(IBLKS, J_), 128>>>(W1, W2, B1, B2);
    reduce_kernel<<<(B_ * J_ + 255) / 256, 256>>>(out);
}

// round 6
// speedup vs baseline: 2.1617x; 1.4136x over previous
#include <cuda_runtime.h>
#include <cuda_fp16.h>

// Problem constants
#define B_  256
#define I_  128
#define J_  128
#define H_  32
#define FP_ 8          // padded feature count; f7 = 1.0 bias lane
#define ITILE 16
#define IBLKS (I_ / ITILE)   // 8

// Scratch (allocation-free rule: __device__ globals)
__device__ __align__(16) __half g_feats_h[I_ * B_ * FP_];  // [i][b][f0..f7]
__device__ float g_partial[IBLKS * B_ * J_];               // [ib][j][b]

__device__ __forceinline__ __half2 h2u(unsigned u) {
    return *reinterpret_cast<__half2*>(&u);
}
__device__ __forceinline__ unsigned u32h2(__half2 h) {
    return *reinterpret_cast<unsigned*>(&h);
}

// Kernel 1: feats[i][b][8] = half{x, sin x, sin 2x, sin 4x, cos x, cos 2x, cos 4x, 1}
__global__ __launch_bounds__(256) void feats_kernel(const float* __restrict__ x) {
    int t = blockIdx.x * 256 + threadIdx.x;   // t = i*256 + b
    int i = t >> 8, b = t & 255;
    float xi = x[b * I_ + i];                  // strided read; x is tiny & L2-hot
    float s1, c1, s2, c2, s4, c4;
    __sincosf(xi, &s1, &c1);
    __sincosf(2.0f * xi, &s2, &c2);
    __sincosf(4.0f * xi, &s4, &c4);
    __half2 p0 = __floats2half2_rn(xi, s1);   // lo = f0, hi = f1
    __half2 p1 = __floats2half2_rn(s2, s4);
    __half2 p2 = __floats2half2_rn(c1, c2);
    __half2 p3 = __floats2half2_rn(c4, 1.0f); // f7 = bias lane
    uint4 v = make_uint4(u32h2(p0), u32h2(p1), u32h2(p2), u32h2(p3));
    *reinterpret_cast<uint4*>(&g_feats_h[(size_t)t * FP_]) = v;   // coalesced 16B
}

// Kernel 2: block = (i-tile of 16, j), 128 threads (4 warps). Warp w owns b-range
// [w*64, w*64+64) as 4 m16n8k8 m-tiles. u = 0.5*(W1·feats + B1) via HMMA (fp32 acc),
// silu in fp16x2, W2 contraction in fp32. Per-b h-sum finished with shfl over lane%4.
__global__ void __launch_bounds__(128, 8) kan_main_kernel(
    const float* __restrict__ W1,   // [I,J,H,7]
    const float* __restrict__ W2,   // [I,J,1,H]
    const float* __restrict__ B1,   // [I,J,H]
    const float* __restrict__ B2)   // [I,J,1]
{
    __shared__ __align__(16) __half w1h[ITILE][H_][FP_];  // 0.5*W1, f7 = 0.5*B1
    __shared__ float w2f[ITILE][H_];
    __shared__ float b2s[ITILE];

    const int j   = blockIdx.y;
    const int i0  = blockIdx.x * ITILE;
    const int tid = threadIdx.x;

    // Stage 0.5*W1 (+0.5*B1 in f7) as half
    for (int idx = tid; idx < ITILE * H_ * FP_; idx += 128) {
        int il = idx >> 8;            // H_*FP_ = 256
        int r  = idx & 255;
        int h  = r >> 3;
        int f  = r & 7;
        size_t ij = (size_t)(i0 + il) * J_ + j;
        float v = (f < 7) ? W1[ij * (H_ * 7) + h * 7 + f] : B1[ij * H_ + h];
        w1h[il][h][f] = __float2half(0.5f * v);
    }
    for (int idx = tid; idx < ITILE * H_; idx += 128) {
        int il = idx >> 5, h = idx & 31;
        w2f[il][h] = W2[((size_t)(i0 + il) * J_ + j) * H_ + h];
    }
    if (tid < ITILE) b2s[tid] = B2[(size_t)(i0 + tid) * J_ + j];
    __syncthreads();

    const int lane = tid & 31, warp = tid >> 5;
    const int gid = lane >> 2;      // groupID  (fragment row selector)
    const int tig = lane & 3;       // threadID-in-group (fragment col selector)
    const int wbase = warp * 64;

    float bsum = 0.0f;
    #pragma unroll
    for (int il = 0; il < ITILE; il++) bsum += b2s[il];

    float acc[4][2] = {};           // [m-tile][row-half (b vs b+8)]
    const float fzero = 0.0f;

    for (int il = 0; il < ITILE; il++) {
        const __half* fbase = g_feats_h + (size_t)(i0 + il) * (B_ * FP_);

        #pragma unroll
        for (int mt = 0; mt < 4; mt++) {
            int brow = wbase + mt * 16 + gid;
            // A fragment: rows (brow, brow+8), cols f = tig*2, tig*2+1. Coalesced LDG.
            unsigned a0 = *reinterpret_cast<const unsigned*>(fbase + brow * FP_ + tig * 2);
            unsigned a1 = *reinterpret_cast<const unsigned*>(fbase + (brow + 8) * FP_ + tig * 2);

            #pragma unroll
            for (int hg = 0; hg < 4; hg++) {
                int h0 = hg * 8;
                // B fragment: thread holds (k = tig*2, tig*2+1; n = gid)
                unsigned b0 = *reinterpret_cast<const unsigned*>(&w1h[il][h0 + gid][tig * 2]);
                // C cols owned by this thread: h = h0 + tig*2, +1
                float2 w2v = *reinterpret_cast<const float2*>(&w2f[il][h0 + tig * 2]);

                float d0, d1, d2, d3;
                asm volatile(
                    "mma.sync.aligned.m16n8k8.row.col.f32.f16.f16.f32 "
                    "{%0,%1,%2,%3}, {%4,%5}, {%6}, {%7,%8,%9,%10};"
                    : "=f"(d0), "=f"(d1), "=f"(d2), "=f"(d3)
                    : "r"(a0), "r"(a1), "r"(b0),
                      "f"(fzero), "f"(fzero), "f"(fzero), "f"(fzero));

                // d0,d1 = (row brow,   cols h0+tig*2, +1) = u values
                // d2,d3 = (row brow+8, cols h0+tig*2, +1)
                unsigned u01, u23;
                asm("cvt.rn.f16x2.f32 %0, %1, %2;" : "=r"(u01) : "f"(d1), "f"(d0));
                asm("cvt.rn.f16x2.f32 %0, %1, %2;" : "=r"(u23) : "f"(d3), "f"(d2));
                unsigned t01, t23;
                asm("tanh.approx.f16x2 %0, %1;" : "=r"(t01) : "r"(u01));
                asm("tanh.approx.f16x2 %0, %1;" : "=r"(t23) : "r"(u23));
                // silu(t) = u + u*tanh(u)  with u = t/2
                __half2 s01 = __hfma2(h2u(u01), h2u(t01), h2u(u01));
                __half2 s23 = __hfma2(h2u(u23), h2u(t23), h2u(u23));
                float2 f01 = __half22float2(s01);
                float2 f23 = __half22float2(s23);
                acc[mt][0] = fmaf(f01.y, w2v.y, fmaf(f01.x, w2v.x, acc[mt][0]));
                acc[mt][1] = fmaf(f23.y, w2v.y, fmaf(f23.x, w2v.x, acc[mt][1]));
            }
        }
    }

    // Finish h-sum across the 4 lanes sharing gid (they hold the other h's of the same b)
    float* gp = g_partial + blockIdx.x * (B_ * J_) + j * B_;
    #pragma unroll
    for (int mt = 0; mt < 4; mt++) {
        #pragma unroll
        for (int hh = 0; hh < 2; hh++) {
            float v = acc[mt][hh];
            v += __shfl_xor_sync(0xffffffffu, v, 1);
            v += __shfl_xor_sync(0xffffffffu, v, 2);
            if (tig == 0)
                gp[wbase + mt * 16 + gid + hh * 8] = v + bsum;
        }
    }
}

// Kernel 3: reduce the 8 i-tile partials.
__global__ void reduce_kernel(float* __restrict__ out) {
    int t = blockIdx.x * blockDim.x + threadIdx.x;
    if (t >= B_ * J_) return;
    int b = t & (B_ - 1);
    int j = t >> 8;                 // t = j*B + b
    float s = 0.0f;
    #pragma unroll
    for (int k = 0; k < IBLKS; k++)
        s += g_partial[k * (B_ * J_) + j * B_ + b];
    out[b * J_ + j] = s;
}

extern "C" void kernel_launch(void* const* d_in, const int* in_sizes, int n_in,
                              void* d_out, int out_size) {
    const float* x  = (const float*)d_in[0];
    const float* W1 = (const float*)d_in[1];
    const float* W2 = (const float*)d_in[2];
    const float* B1 = (const float*)d_in[3];
    const float* B2 = (const float*)d_in[4];
    float* out = (float*)d_out;

    feats_kernel<<<(B_ * I_) / 256, 256>>>(x);
    kan_main_kernel<<<dim3(IBLKS, J_), 128>>>(W1, W2, B1, B2);
    reduce_kernel<<<(B_ * J_ + 255) / 256, 256>>>(out);
}

// round 7
// speedup vs baseline: 2.2600x; 1.0455x over previous
#include <cuda_runtime.h>
#include <cuda_fp16.h>

// Problem constants
#define B_  256
#define I_  128
#define J_  128
#define H_  32
#define FP_ 8          // padded feature count; f7 = 1.0 bias lane
#define ITILE 16
#define IBLKS (I_ / ITILE)   // 8

// Scratch (allocation-free rule: __device__ globals)
__device__ __align__(16) __half g_feats_h[I_ * B_ * FP_];  // [i][b][f0..f7]
__device__ float g_partial[IBLKS * B_ * J_];               // [ib][j][b]

__device__ __forceinline__ unsigned u32h2(__half2 h) {
    return *reinterpret_cast<unsigned*>(&h);
}
__device__ __forceinline__ unsigned hfma2u(unsigned a, unsigned b, unsigned c) {
    unsigned d;
    asm("fma.rn.f16x2 %0, %1, %2, %3;" : "=r"(d) : "r"(a), "r"(b), "r"(c));
    return d;
}
__device__ __forceinline__ unsigned tanh2u(unsigned a) {
    unsigned d;
    asm("tanh.approx.f16x2 %0, %1;" : "=r"(d) : "r"(a));
    return d;
}

// Kernel 1: feats[i][b][8] = half{x, sin x, sin 2x, sin 4x, cos x, cos 2x, cos 4x, 1}
// t = b*128 + i so x loads are fully coalesced; 16B stores scatter (no stall).
__global__ __launch_bounds__(256) void feats_kernel(const float* __restrict__ x) {
    int t = blockIdx.x * 256 + threadIdx.x;   // t = b*I + i
    int b = t >> 7, i = t & 127;
    float xi = x[t];                          // coalesced
    float s1, c1, s2, c2, s4, c4;
    __sincosf(xi, &s1, &c1);
    __sincosf(2.0f * xi, &s2, &c2);
    __sincosf(4.0f * xi, &s4, &c4);
    __half2 p0 = __floats2half2_rn(xi, s1);
    __half2 p1 = __floats2half2_rn(s2, s4);
    __half2 p2 = __floats2half2_rn(c1, c2);
    __half2 p3 = __floats2half2_rn(c4, 1.0f);  // f7 = bias lane
    uint4 v = make_uint4(u32h2(p0), u32h2(p1), u32h2(p2), u32h2(p3));
    *reinterpret_cast<uint4*>(&g_feats_h[((size_t)i * B_ + b) * FP_]) = v;
}

// Kernel 2: block = (i-tile of 16, j), 128 threads (4 warps). Warp w owns 64 b-rows
// as 4 m16n8k8 m-tiles.
//  - u = 0.5*(W1·feats + B1): m16n8k8 HMMA, fp16 accumulator (D = f16x2 regs, no cvt)
//  - silu: tanh.approx.f16x2 + HFMA2 (only XU ops in the loop)
//  - Σ_h s·W2: m16n8k16 HMMA, W2 fp16 replicated over n-cols, fp32 accumulator
__global__ void __launch_bounds__(128, 8) kan_main_kernel(
    const float* __restrict__ W1,   // [I,J,H,7]
    const float* __restrict__ W2,   // [I,J,1,H]
    const float* __restrict__ B1,   // [I,J,H]
    const float* __restrict__ B2)   // [I,J,1]
{
    __shared__ __align__(16) __half w1h[ITILE][H_][FP_];  // 0.5*W1, f7 = 0.5*B1
    __shared__ __align__(4)  __half w2h[ITILE][H_];       // W2 as half
    __shared__ float b2s[ITILE];

    const int j   = blockIdx.y;
    const int i0  = blockIdx.x * ITILE;
    const int tid = threadIdx.x;

    // Stage 0.5*W1 (+0.5*B1 in f7) as half
    for (int idx = tid; idx < ITILE * H_ * FP_; idx += 128) {
        int il = idx >> 8;            // H_*FP_ = 256
        int r  = idx & 255;
        int h  = r >> 3;
        int f  = r & 7;
        size_t ij = (size_t)(i0 + il) * J_ + j;
        float v = (f < 7) ? W1[ij * (H_ * 7) + h * 7 + f] : B1[ij * H_ + h];
        w1h[il][h][f] = __float2half(0.5f * v);
    }
    for (int idx = tid; idx < ITILE * H_; idx += 128) {
        int il = idx >> 5, h = idx & 31;
        w2h[il][h] = __float2half(W2[((size_t)(i0 + il) * J_ + j) * H_ + h]);
    }
    if (tid < ITILE) b2s[tid] = B2[(size_t)(i0 + tid) * J_ + j];
    __syncthreads();

    const int lane = tid & 31, warp = tid >> 5;
    const int gid = lane >> 2;      // fragment row selector
    const int tig = lane & 3;       // fragment col selector
    const int wbase = warp * 64;

    float bsum = 0.0f;
    #pragma unroll
    for (int il = 0; il < ITILE; il++) bsum += b2s[il];

    float acc[4][4] = {};           // [m-tile][k16-MMA D regs]
    const unsigned zero = 0;

    for (int il = 0; il < ITILE; il++) {
        const __half* fbase = g_feats_h + (size_t)(i0 + il) * (B_ * FP_);

        // A fragments for all 4 m-tiles (coalesced LDG, reused across both hgp)
        unsigned A0[4], A1[4];
        #pragma unroll
        for (int mt = 0; mt < 4; mt++) {
            int brow = wbase + mt * 16 + gid;
            A0[mt] = *reinterpret_cast<const unsigned*>(fbase + brow * FP_ + tig * 2);
            A1[mt] = *reinterpret_cast<const unsigned*>(fbase + (brow + 8) * FP_ + tig * 2);
        }

        #pragma unroll
        for (int hgp = 0; hgp < 2; hgp++) {
            const int h0 = hgp * 16;
            // W1 fragments for hg = 2*hgp (k cols h0..h0+7) and 2*hgp+1
            unsigned wf0 = *reinterpret_cast<const unsigned*>(&w1h[il][h0 + gid][tig * 2]);
            unsigned wf1 = *reinterpret_cast<const unsigned*>(&w1h[il][h0 + 8 + gid][tig * 2]);
            // W2 k16 B-fragments (replicated across n; no gid dependence)
            unsigned wb0 = *reinterpret_cast<const unsigned*>(&w2h[il][h0 + tig * 2]);
            unsigned wb1 = *reinterpret_cast<const unsigned*>(&w2h[il][h0 + 8 + tig * 2]);

            #pragma unroll
            for (int mt = 0; mt < 4; mt++) {
                // u-MMA, fp16 accumulator: D regs are f16x2 (row gid / gid+8)
                unsigned u0, u1, u2, u3;
                asm volatile(
                    "mma.sync.aligned.m16n8k8.row.col.f16.f16.f16.f16 "
                    "{%0,%1}, {%2,%3}, {%4}, {%5,%6};"
                    : "=r"(u0), "=r"(u1)
                    : "r"(A0[mt]), "r"(A1[mt]), "r"(wf0), "r"(zero), "r"(zero));
                asm volatile(
                    "mma.sync.aligned.m16n8k8.row.col.f16.f16.f16.f16 "
                    "{%0,%1}, {%2,%3}, {%4}, {%5,%6};"
                    : "=r"(u2), "=r"(u3)
                    : "r"(A0[mt]), "r"(A1[mt]), "r"(wf1), "r"(zero), "r"(zero));

                // silu(t) = u + u*tanh(u), u = t/2 — pure f16x2
                unsigned s0 = hfma2u(u0, tanh2u(u0), u0);
                unsigned s1 = hfma2u(u1, tanh2u(u1), u1);
                unsigned s2 = hfma2u(u2, tanh2u(u2), u2);
                unsigned s3 = hfma2u(u3, tanh2u(u3), u3);

                // h-contraction: m16n8k16, A = {s0,s1,s2,s3}, B = W2 (replicated),
                // fp32 accumulate into acc[mt]
                asm volatile(
                    "mma.sync.aligned.m16n8k16.row.col.f32.f16.f16.f32 "
                    "{%0,%1,%2,%3}, {%4,%5,%6,%7}, {%8,%9}, {%0,%1,%2,%3};"
                    : "+f"(acc[mt][0]), "+f"(acc[mt][1]),
                      "+f"(acc[mt][2]), "+f"(acc[mt][3])
                    : "r"(s0), "r"(s1), "r"(s2), "r"(s3), "r"(wb0), "r"(wb1));
            }
        }
    }

    // Every thread holds the full per-b sums (B replicated) — tig==0 lanes store.
    // acc[mt][0] = row (wbase+mt*16+gid), acc[mt][2] = row +8.
    float* gp = g_partial + blockIdx.x * (B_ * J_) + j * B_;
    if (tig == 0) {
        #pragma unroll
        for (int mt = 0; mt < 4; mt++) {
            int brow = wbase + mt * 16 + gid;
            gp[brow]     = acc[mt][0] + bsum;
            gp[brow + 8] = acc[mt][2] + bsum;
        }
    }
}

// Kernel 3: reduce the 8 i-tile partials.
__global__ void reduce_kernel(float* __restrict__ out) {
    int t = blockIdx.x * blockDim.x + threadIdx.x;
    if (t >= B_ * J_) return;
    int b = t & (B_ - 1);
    int j = t >> 8;                 // t = j*B + b
    float s = 0.0f;
    #pragma unroll
    for (int k = 0; k < IBLKS; k++)
        s += g_partial[k * (B_ * J_) + j * B_ + b];
    out[b * J_ + j] = s;
}

extern "C" void kernel_launch(void* const* d_in, const int* in_sizes, int n_in,
                              void* d_out, int out_size) {
    const float* x  = (const float*)d_in[0];
    const float* W1 = (const float*)d_in[1];
    const float* W2 = (const float*)d_in[2];
    const float* B1 = (const float*)d_in[3];
    const float* B2 = (const float*)d_in[4];
    float* out = (float*)d_out;

    feats_kernel<<<(B_ * I_) / 256, 256>>>(x);
    kan_main_kernel<<<dim3(IBLKS, J_), 128>>>(W1, W2, B1, B2);
    reduce_kernel<<<(B_ * J_ + 255) / 256, 256>>>(out);
}